// round 1
// baseline (speedup 1.0000x reference)
#include <cuda_runtime.h>
#include <cuda_bf16.h>

// x: [B=32, C=256, W=56, H=56] fp32, contiguous.
// Groups of 4 consecutive channels. Keep elements that are the group max AND > 0,
// clamped to max_clamp; zero otherwise.
//
// Geometry (in float4 units):
//   spatial plane per channel: 56*56 = 3136 floats = 784 float4
//   one channel-group (4 channels) = 4*784 = 3136 float4, contiguous
//   number of groups total = 32 * 64 = 2048
//   threads = 2048 * 784 = 1,605,632; each reads 4x float4, writes 4x float4.

static constexpr int F4_PER_PLANE = 784;     // 3136 floats / 4
static constexpr int F4_PER_GROUP = 3136;    // 4 channels * 784
static constexpr int TOTAL_THREADS = 2048 * F4_PER_PLANE;  // 1,605,632

__global__ __launch_bounds__(256) void CGM_16707422781821_kernel(
    const float4* __restrict__ x,
    float4* __restrict__ out,
    const float* __restrict__ max_clamp_p)
{
    int idx = blockIdx.x * blockDim.x + threadIdx.x;
    if (idx >= TOTAL_THREADS) return;

    const float mc = __ldg(max_clamp_p);

    // idx -> (group_block gb, spatial float4 s)
    int gb = idx / F4_PER_PLANE;
    int s  = idx - gb * F4_PER_PLANE;
    long base = (long)gb * F4_PER_GROUP + s;

    // Load the 4 channels of this group at this spatial float4.
    float4 v0 = x[base];
    float4 v1 = x[base + F4_PER_PLANE];
    float4 v2 = x[base + 2 * F4_PER_PLANE];
    float4 v3 = x[base + 3 * F4_PER_PLANE];

    // Componentwise group max.
    float mx_x = fmaxf(fmaxf(v0.x, v1.x), fmaxf(v2.x, v3.x));
    float mx_y = fmaxf(fmaxf(v0.y, v1.y), fmaxf(v2.y, v3.y));
    float mx_z = fmaxf(fmaxf(v0.z, v1.z), fmaxf(v2.z, v3.z));
    float mx_w = fmaxf(fmaxf(v0.w, v1.w), fmaxf(v2.w, v3.w));

    // Mask: keep = (v == max) && (v > 0); value = min(v, mc) else 0.
    #define MASK1(v, m) (((v) == (m) && (v) > 0.0f) ? fminf((v), mc) : 0.0f)
    #define MASK4(v) do { \
        v.x = MASK1(v.x, mx_x); \
        v.y = MASK1(v.y, mx_y); \
        v.z = MASK1(v.z, mx_z); \
        v.w = MASK1(v.w, mx_w); \
    } while (0)

    MASK4(v0);
    MASK4(v1);
    MASK4(v2);
    MASK4(v3);

    out[base]                    = v0;
    out[base + F4_PER_PLANE]     = v1;
    out[base + 2 * F4_PER_PLANE] = v2;
    out[base + 3 * F4_PER_PLANE] = v3;

    #undef MASK4
    #undef MASK1
}

extern "C" void kernel_launch(void* const* d_in, const int* in_sizes, int n_in,
                              void* d_out, int out_size) {
    const float4* x = (const float4*)d_in[0];
    // d_in[1] = group_size (int32, == 4, baked into the kernel geometry)
    const float* max_clamp_p = (const float*)d_in[2];
    float4* out = (float4*)d_out;

    const int threads = 256;
    const int blocks = (TOTAL_THREADS + threads - 1) / threads;  // 6272
    CGM_16707422781821_kernel<<<blocks, threads>>>(x, out, max_clamp_p);
}